// round 16
// baseline (speedup 1.0000x reference)
#include <cuda_runtime.h>
#include <cuda_bf16.h>
#include <math.h>

// ---------------------------------------------------------------------------
// AsymmetricLossCustomPriorityRankNewNegOne  (B=4096, C=9605, L=20)
// THREE launches:
//   build_bits : per-class group bitmask, FULLY-UNROLLED L loop (1 load epoch),
//                per-block partials as plain stores, block 0 zeroes out
//   finalize   : 1 block reduces partials + verifies fast path (L2-hot)
//   row_loss   : warp-per-row probe + batched epochs (round-14 main, 13.8us)
// Fast path device-verified; slow path scans g_bits directly (safety net).
// ---------------------------------------------------------------------------

#define MAXC 16384
#define JINF 0x7fffffff
#define LMAX 32

__device__ unsigned g_bits[MAXC];
__device__ int4     g_part[256];    // per-block {bmin, bmax, bbad, bgs}
__device__ int      g_cmin, g_n, g_gs, g_notfast;

__device__ __forceinline__ unsigned enc_f(float f) {
    unsigned u = __float_as_uint(f);
    return (u & 0x80000000u) ? ~u : (u | 0x80000000u);
}
__device__ __forceinline__ float dec_f(unsigned u) {
    return __uint_as_float((u & 0x80000000u) ? (u & 0x7fffffffu) : ~u);
}
__device__ __forceinline__ float sigmoidf_(float x) {
    return 1.0f / (1.0f + expf(-x));
}
// d = x2 - x1 + 0.05; s = sigmoid(10 d); d>0 -> 2s else s
__device__ __forceinline__ float rank_loss_(float x1, float x2) {
    float d = x2 - x1 + 0.05f;
    float s = sigmoidf_(10.0f * d);
    return (d > 0.0f) ? 2.0f * s : s;
}

// --- kernel 1: build bits + per-block partials ----------------------------------
__global__ __launch_bounds__(128)
void build_bits_kernel(const void* wl, int C, int L, float* out, int out_size) {
    __shared__ int su8, sbmin, sbmax, sbbad, sbgs;
    const int tid = threadIdx.x;
    if (tid == 0) { su8 = 0; sbmin = 0x7fffffff; sbmax = -1; sbbad = 0; sbgs = 0; }
    __syncthreads();

    // width probe (epoch 1): read first 512B as u32. In u8 layout group 0's
    // ones (bytes [0,50)) give values like 0x01010101 > 1; in i32 layout all
    // probed values are 0/1. Identical result in every block (L2-hot).
    {
        const unsigned v = ((const unsigned*)wl)[tid];
        if (v > 1u) atomicOr(&su8, 1);
    }
    __syncthreads();
    const int is_u8 = su8;

    // mask loads (epoch 2): ALL L loads in flight (compile-time unroll)
    const int c = blockIdx.x * blockDim.x + tid;
    if (c < C) {
        unsigned b = 0;
        if (is_u8) {
            const unsigned char* m = (const unsigned char*)wl;
            #pragma unroll
            for (int l = 0; l < LMAX; l++)
                if (l < L && m[(size_t)l * C + c]) b |= (1u << l);
        } else {
            const int* m = (const int*)wl;
            #pragma unroll
            for (int l = 0; l < LMAX; l++)
                if (l < L && m[(size_t)l * C + c]) b |= (1u << l);
        }
        g_bits[c] = b;
        if (b) {
            atomicMin(&sbmin, c);
            atomicMax(&sbmax, c);
            if (__popc(b) > 1) atomicOr(&sbbad, 1);
            if (b == 1u) atomicAdd(&sbgs, 1);       // class in group 0 only
        }
    }
    // block 0 zeroes the (0xAA-poisoned) output
    if (blockIdx.x == 0)
        for (int i = tid; i < out_size; i += blockDim.x) out[i] = 0.0f;
    __syncthreads();
    if (tid == 0) g_part[blockIdx.x] = make_int4(sbmin, sbmax, sbbad, sbgs);
}

// --- kernel 2: finalize (1 block): reduce partials + verify fast path ------------
__global__ __launch_bounds__(1024)
void finalize_kernel(int C, int nblocks) {
    __shared__ int rmin, rmax, rbad, rgs, rcount;
    const int tid = threadIdx.x;
    if (tid == 0) { rmin = 0x7fffffff; rmax = -1; rbad = 0; rgs = 0; rcount = 0; }
    __syncthreads();

    if (tid < nblocks) {
        const int4 pp = g_part[tid];
        if (pp.y >= 0) { atomicMin(&rmin, pp.x); atomicMax(&rmax, pp.y); }
        if (pp.z) atomicOr(&rbad, 1);
        atomicAdd(&rgs, pp.w);
    }
    __syncthreads();
    const int cmin = rmin, cmax = rmax, gs = rgs;

    // count union classes + verify magic-division gid exactly (L2-hot scan)
    int mycount = 0, mybad = 0;
    if (gs > 0 && cmax >= 0) {
        const unsigned M = (4194304u + (unsigned)gs - 1u) / (unsigned)gs;
        for (int cc = tid; cc < C; cc += 1024) {
            const unsigned bb = g_bits[cc];
            if (bb) {
                mycount++;
                const unsigned gm = ((unsigned)(cc - cmin) * M) >> 22;
                if ((int)gm != (__ffs(bb) - 1) || gm >= 32u) mybad = 1;
            }
        }
    } else {
        mybad = 1;
    }
    if (mycount) atomicAdd(&rcount, mycount);
    if (mybad)   atomicOr(&rbad, 1);
    __syncthreads();
    if (tid == 0) {
        int nf = rbad;
        if (cmax < 0 || (cmax - cmin + 1) != rcount) nf = 1;
        g_cmin = cmin; g_n = rcount; g_gs = gs; g_notfast = nf;
    }
}

// --- kernel 3: warp-per-row loss, probe + batched epochs (round-14 main) --------
__global__ __launch_bounds__(128, 6)
void row_loss_kernel(const float* __restrict__ x,
                     const int*   __restrict__ y,
                     const int*   __restrict__ yneg,
                     int C, int B, float* __restrict__ out) {
    __shared__ float sSum;
    __shared__ unsigned sG[4][32];           // slow path per-warp group maxes

    const int lane = threadIdx.x & 31;
    const int wid  = threadIdx.x >> 5;
    const int row  = wid * gridDim.x + blockIdx.x;   // strided: mix wl/other

    if (threadIdx.x == 0) sSum = 0.0f;
    __syncthreads();

    const int n    = g_n;
    const int cmin = g_cmin;
    const bool fast = !g_notfast;

    float warp_loss = 0.0f;

    if (row < B && fast) {
        const int gs = g_gs;
        const unsigned M = (4194304u + (unsigned)gs - 1u) / (unsigned)gs;
        const long long base = (long long)row * C + cmin;
        const float* __restrict__ xr  = x    + base;
        const int*   __restrict__ yr  = y    + base;
        const int*   __restrict__ ynr = yneg + base;

        int p = (int)((4 - (base & 3)) & 3);
        if (p > n) p = n;
        const int nv = (n - p) >> 2;          // vec4 chunks
        const int ts = p + 4 * nv;
        const int ntail = n - ts;

        int jmin = JINF;

        // ======= epoch 0: probe peel + first 32 chunks (j < p+128) ==========
        {
            const int ypeel = (lane < p) ? __ldg(yr + lane) : 0;
            int4 yv = (lane < nv) ? __ldg((const int4*)(yr + p + 4 * lane))
                                  : make_int4(0, 0, 0, 0);
            if (yv.x | yv.y | yv.z | yv.w) {
                const int j0 = p + 4 * lane;
                if      (yv.x) jmin = j0;
                else if (yv.y) jmin = j0 + 1;
                else if (yv.z) jmin = j0 + 2;
                else           jmin = j0 + 3;
            }
            if (ypeel && lane < jmin) jmin = lane;
            #pragma unroll
            for (int off = 16; off > 0; off >>= 1)
                jmin = min(jmin, __shfl_xor_sync(0xffffffffu, jmin, off));
        }

        // ======= epoch 1: remaining y chunks, batched 8/lane ================
        if (jmin == JINF) {
            for (int b0 = 32; b0 < nv; b0 += 256) {
                int4 yv[8];
                #pragma unroll
                for (int k = 0; k < 8; k++) {
                    const int i = b0 + lane + k * 32;
                    yv[k] = (i < nv) ? __ldg((const int4*)(yr + p + 4 * i))
                                     : make_int4(0, 0, 0, 0);
                }
                #pragma unroll
                for (int k = 0; k < 8; k++) {
                    const int i = b0 + lane + k * 32;
                    if ((yv[k].x | yv[k].y | yv[k].z | yv[k].w) &&
                        i < nv && jmin == JINF) {
                        const int j0 = p + 4 * i;
                        if      (yv[k].x) jmin = j0;
                        else if (yv[k].y) jmin = j0 + 1;
                        else if (yv[k].z) jmin = j0 + 2;
                        else              jmin = j0 + 3;
                    }
                }
                if (__any_sync(0xffffffffu, jmin != JINF)) break;
            }
            // tail [ts, n)
            if (__all_sync(0xffffffffu, jmin == JINF) && ntail > 0) {
                const int ytv = (lane < ntail) ? __ldg(yr + ts + lane) : 0;
                if (ytv) jmin = ts + lane;
            }
            #pragma unroll
            for (int off = 16; off > 0; off >>= 1)
                jmin = min(jmin, __shfl_xor_sync(0xffffffffu, jmin, off));
        }

        if (jmin != JINF) {
            // ======= epoch 2a: priority group's x (gs floats) ===============
            const int fl = (int)(((unsigned)jmin * M) >> 22);
            const int j0 = fl * gs;
            float m = -1e30f;
            for (int t = lane; t < gs; t += 32) {
                const int j = j0 + t;
                if (j < n) m = fmaxf(m, __ldg(xr + j));
            }
            #pragma unroll
            for (int off = 16; off > 0; off >>= 1)
                m = fmaxf(m, __shfl_xor_sync(0xffffffffu, m, off));
            warp_loss = rank_loss_(sigmoidf_(m), 0.5f);
        } else {
            // ======= epoch 2b: x & y_neg, 16 loads in flight ================
            float mN = -1e30f, mW = -1e30f;
            if (lane < p) {
                const float xv = __ldg(xr + lane);
                mN = fmaxf(mN, xv);
                mW = fmaxf(mW, __ldg(ynr + lane) ? xv : -1e30f);
            }
            if (lane < ntail) {
                const int j = ts + lane;
                const float xv = __ldg(xr + j);
                mN = fmaxf(mN, xv);
                mW = fmaxf(mW, __ldg(ynr + j) ? xv : -1e30f);
            }
            for (int b0 = 0; b0 < nv; b0 += 256) {
                float4 xv[8];
                int4   nvv[8];
                #pragma unroll
                for (int k = 0; k < 8; k++) {
                    const int i = b0 + lane + k * 32;
                    const int j0 = p + 4 * i;
                    if (i < nv) {
                        xv[k]  = __ldg((const float4*)(xr  + j0));
                        nvv[k] = __ldg((const int4*)  (ynr + j0));
                    } else {
                        xv[k]  = make_float4(-1e30f, -1e30f, -1e30f, -1e30f);
                        nvv[k] = make_int4(0, 0, 0, 0);
                    }
                }
                #pragma unroll
                for (int k = 0; k < 8; k++) {
                    mN = fmaxf(mN, fmaxf(fmaxf(xv[k].x, xv[k].y),
                                         fmaxf(xv[k].z, xv[k].w)));
                    mW = fmaxf(mW, nvv[k].x ? xv[k].x : -1e30f);
                    mW = fmaxf(mW, nvv[k].y ? xv[k].y : -1e30f);
                    mW = fmaxf(mW, nvv[k].z ? xv[k].z : -1e30f);
                    mW = fmaxf(mW, nvv[k].w ? xv[k].w : -1e30f);
                }
            }
            #pragma unroll
            for (int off = 16; off > 0; off >>= 1) {
                mN = fmaxf(mN, __shfl_xor_sync(0xffffffffu, mN, off));
                mW = fmaxf(mW, __shfl_xor_sync(0xffffffffu, mW, off));
            }
            warp_loss = 0.5f * rank_loss_(0.5f, sigmoidf_(mN))
                      + 0.5f * rank_loss_(0.5f, sigmoidf_(mW));
        }
    } else if (row < B) {
        // ---------------- generic slow path: scan g_bits over [0, C) ----------
        const unsigned KNEG = enc_f(-1e30f);
        sG[wid][lane] = KNEG;
        __syncwarp();

        unsigned locNon = KNEG, locWrong = KNEG, locPres = 0u;
        for (int c = lane; c < C; c += 32) {
            const unsigned bits = g_bits[c];
            if (!bits) continue;
            const long long o = (long long)row * C + c;
            const float xv = __ldg(x + o);
            const unsigned key = enc_f(xv);
            locNon = max(locNon, key);
            if (__ldg(yneg + o) != 0) locWrong = max(locWrong, key);
            if (__ldg(y    + o) != 0) locPres |= bits;
            unsigned bb = bits;
            while (bb) {
                const int l = __ffs(bb) - 1;
                bb &= bb - 1u;
                atomicMax(&sG[wid][l], key);
            }
        }
        #pragma unroll
        for (int off = 16; off > 0; off >>= 1) {
            locNon   = max(locNon,   __shfl_xor_sync(0xffffffffu, locNon,   off));
            locWrong = max(locWrong, __shfl_xor_sync(0xffffffffu, locWrong, off));
            locPres |= __shfl_xor_sync(0xffffffffu, locPres, off);
        }
        __syncwarp();
        if (lane == 0) {
            if (locPres) {
                const int fl = __ffs(locPres) - 1;
                warp_loss = rank_loss_(sigmoidf_(dec_f(sG[wid][fl])), 0.5f);
            } else {
                warp_loss = 0.5f * rank_loss_(0.5f, sigmoidf_(dec_f(locNon)))
                          + 0.5f * rank_loss_(0.5f, sigmoidf_(dec_f(locWrong)));
            }
        }
    }

    if (lane == 0 && row < B) atomicAdd(&sSum, warp_loss);
    __syncthreads();
    if (threadIdx.x == 0) atomicAdd(out, sSum);
}

// ---------------------------------------------------------------------------
extern "C" void kernel_launch(void* const* d_in, const int* in_sizes, int n_in,
                              void* d_out, int out_size) {
    const float* x    = (const float*)d_in[0];
    const int*   y    = (const int*)d_in[1];
    const int*   yneg = (const int*)d_in[2];
    const void*  wl   = d_in[3];

    const int C = 9605;
    const int L = in_sizes[3] / C;            // 20
    const int B = in_sizes[0] / C;            // 4096

    float* out = (float*)d_out;

    const int nb = (C + 127) / 128;           // 76 blocks (fits g_part[256])

    build_bits_kernel<<<nb, 128>>>(wl, C, L, out, out_size);
    finalize_kernel<<<1, 1024>>>(C, nb);
    row_loss_kernel<<<(B + 3) / 4, 128>>>(x, y, yneg, C, B, out);
}

// round 17
// speedup vs baseline: 1.1530x; 1.1530x over previous
#include <cuda_runtime.h>
#include <cuda_bf16.h>
#include <math.h>

// ---------------------------------------------------------------------------
// AsymmetricLossCustomPriorityRankNewNegOne  (B=4096, C=9605, L=20)
// THREE launches:
//   build_bits : per-class group bitmask + per-block partials (r15 version)
//   finalize   : 1 block reduces partials + verifies fast path (L2-hot)
//   row_loss   : warp-per-row, TWO epochs, ONE resident wave (128thr x 7/SM)
// Fast path device-verified; slow path scans g_bits directly (safety net).
// ---------------------------------------------------------------------------

#define MAXC 16384
#define JINF 0x7fffffff

__device__ unsigned g_bits[MAXC];
__device__ int4     g_part[256];    // per-block {bmin, bmax, bbad, bgs}
__device__ int      g_cmin, g_n, g_gs, g_notfast;

__device__ __forceinline__ unsigned enc_f(float f) {
    unsigned u = __float_as_uint(f);
    return (u & 0x80000000u) ? ~u : (u | 0x80000000u);
}
__device__ __forceinline__ float dec_f(unsigned u) {
    return __uint_as_float((u & 0x80000000u) ? (u & 0x7fffffffu) : ~u);
}
__device__ __forceinline__ float sigmoidf_(float x) {
    return 1.0f / (1.0f + expf(-x));
}
// d = x2 - x1 + 0.05; s = sigmoid(10 d); d>0 -> 2s else s
__device__ __forceinline__ float rank_loss_(float x1, float x2) {
    float d = x2 - x1 + 0.05f;
    float s = sigmoidf_(10.0f * d);
    return (d > 0.0f) ? 2.0f * s : s;
}

// --- kernel 1: build bits + per-block partials (r15 banked version) -------------
__global__ __launch_bounds__(256)
void build_bits_kernel(const void* wl, int C, int L, float* out, int out_size) {
    __shared__ int su8, sbmin, sbmax, sbbad, sbgs;
    const int tid = threadIdx.x;
    if (tid == 0) { su8 = 0; sbmin = 0x7fffffff; sbmax = -1; sbbad = 0; sbgs = 0; }
    __syncthreads();

    // width probe: u8 layout packs group-0 ones into u32 values > 1
    {
        const unsigned v = ((const unsigned*)wl)[tid];
        if (v > 1u) atomicOr(&su8, 1);
    }
    __syncthreads();
    const int is_u8 = su8;

    const int c = blockIdx.x * blockDim.x + tid;
    if (c < C) {
        unsigned b = 0;
        if (is_u8) {
            const unsigned char* m = (const unsigned char*)wl;
            #pragma unroll 4
            for (int l = 0; l < L; l++)
                if (m[(size_t)l * C + c]) b |= (1u << l);
        } else {
            const int* m = (const int*)wl;
            #pragma unroll 4
            for (int l = 0; l < L; l++)
                if (m[(size_t)l * C + c]) b |= (1u << l);
        }
        g_bits[c] = b;
        if (b) {
            atomicMin(&sbmin, c);
            atomicMax(&sbmax, c);
            if (__popc(b) > 1) atomicOr(&sbbad, 1);
            if (b == 1u) atomicAdd(&sbgs, 1);       // class in group 0 only
        }
    }
    if (blockIdx.x == 0)
        for (int i = tid; i < out_size; i += blockDim.x) out[i] = 0.0f;
    __syncthreads();
    if (tid == 0) g_part[blockIdx.x] = make_int4(sbmin, sbmax, sbbad, sbgs);
}

// --- kernel 2: finalize (1 block): reduce partials + verify fast path ------------
__global__ __launch_bounds__(1024)
void finalize_kernel(int C, int nblocks) {
    __shared__ int rmin, rmax, rbad, rgs, rcount;
    const int tid = threadIdx.x;
    if (tid == 0) { rmin = 0x7fffffff; rmax = -1; rbad = 0; rgs = 0; rcount = 0; }
    __syncthreads();

    if (tid < nblocks) {
        const int4 pp = g_part[tid];
        if (pp.y >= 0) { atomicMin(&rmin, pp.x); atomicMax(&rmax, pp.y); }
        if (pp.z) atomicOr(&rbad, 1);
        atomicAdd(&rgs, pp.w);
    }
    __syncthreads();
    const int cmin = rmin, cmax = rmax, gs = rgs;

    int mycount = 0, mybad = 0;
    if (gs > 0 && cmax >= 0) {
        const unsigned M = (4194304u + (unsigned)gs - 1u) / (unsigned)gs;
        for (int cc = tid; cc < C; cc += 1024) {
            const unsigned bb = g_bits[cc];
            if (bb) {
                mycount++;
                const unsigned gm = ((unsigned)(cc - cmin) * M) >> 22;
                if ((int)gm != (__ffs(bb) - 1) || gm >= 32u) mybad = 1;
            }
        }
    } else {
        mybad = 1;
    }
    if (mycount) atomicAdd(&rcount, mycount);
    if (mybad)   atomicOr(&rbad, 1);
    __syncthreads();
    if (tid == 0) {
        int nf = rbad;
        if (cmax < 0 || (cmax - cmin + 1) != rcount) nf = 1;
        g_cmin = cmin; g_n = rcount; g_gs = gs; g_notfast = nf;
    }
}

// --- kernel 3: warp-per-row loss, TWO epochs, one resident wave ------------------
__global__ __launch_bounds__(128, 7)
void row_loss_kernel(const float* __restrict__ x,
                     const int*   __restrict__ y,
                     const int*   __restrict__ yneg,
                     int C, int B, float* __restrict__ out) {
    __shared__ float sSum;
    __shared__ unsigned sG[4][32];           // slow path per-warp group maxes

    const int lane = threadIdx.x & 31;
    const int wid  = threadIdx.x >> 5;
    const int row  = wid * gridDim.x + blockIdx.x;   // strided: mix wl/other

    if (threadIdx.x == 0) sSum = 0.0f;
    __syncthreads();

    const int n    = g_n;
    const int cmin = g_cmin;
    const bool fast = !g_notfast;

    float warp_loss = 0.0f;

    if (row < B && fast) {
        const int gs = g_gs;
        const unsigned M = (4194304u + (unsigned)gs - 1u) / (unsigned)gs;
        const long long base = (long long)row * C + cmin;
        const float* __restrict__ xr  = x    + base;
        const int*   __restrict__ yr  = y    + base;
        const int*   __restrict__ ynr = yneg + base;

        int p = (int)((4 - (base & 3)) & 3);
        if (p > n) p = n;
        const int nv = (n - p) >> 2;          // vec4 chunks (~250 for n~1000)
        const int ts = p + 4 * nv;
        const int ntail = n - ts;

        // ======= epoch 1: FULL y scan, 8 int4 + peel/tail in flight =========
        int jmin = JINF;
        {
            const int ypeel = (lane < p)     ? __ldg(yr + lane)      : 0;
            const int ytail = (lane < ntail) ? __ldg(yr + ts + lane) : 0;
            int4 yv[8];
            #pragma unroll
            for (int k = 0; k < 8; k++) {
                const int i = lane + k * 32;
                yv[k] = (i < nv) ? __ldg((const int4*)(yr + p + 4 * i))
                                 : make_int4(0, 0, 0, 0);
            }
            #pragma unroll
            for (int k = 0; k < 8; k++) {
                if ((yv[k].x | yv[k].y | yv[k].z | yv[k].w) && jmin == JINF) {
                    const int j0 = p + 4 * (lane + k * 32);
                    if      (yv[k].x) jmin = j0;
                    else if (yv[k].y) jmin = j0 + 1;
                    else if (yv[k].z) jmin = j0 + 2;
                    else              jmin = j0 + 3;
                }
            }
            // rare overflow (nv > 256)
            for (int i = 256 + lane; i < nv; i += 32) {
                const int4 yo = __ldg((const int4*)(yr + p + 4 * i));
                if ((yo.x | yo.y | yo.z | yo.w) && jmin == JINF) {
                    const int j0 = p + 4 * i;
                    if      (yo.x) jmin = j0;
                    else if (yo.y) jmin = j0 + 1;
                    else if (yo.z) jmin = j0 + 2;
                    else           jmin = j0 + 3;
                }
            }
            if (ypeel && lane < jmin) jmin = lane;
            if (ytail && jmin == JINF) jmin = ts + lane;
            #pragma unroll
            for (int off = 16; off > 0; off >>= 1)
                jmin = min(jmin, __shfl_xor_sync(0xffffffffu, jmin, off));
        }

        if (jmin != JINF) {
            // ======= epoch 2a: priority group's x (gs floats) ===============
            const int fl = (int)(((unsigned)jmin * M) >> 22);
            const int j0 = fl * gs;
            float m = -1e30f;
            for (int t = lane; t < gs; t += 32) {
                const int j = j0 + t;
                if (j < n) m = fmaxf(m, __ldg(xr + j));
            }
            #pragma unroll
            for (int off = 16; off > 0; off >>= 1)
                m = fmaxf(m, __shfl_xor_sync(0xffffffffu, m, off));
            warp_loss = rank_loss_(sigmoidf_(m), 0.5f);
        } else {
            // ======= epoch 2b: x (8 chunks) + yneg (4+4 chunks) =============
            float mN = -1e30f, mW = -1e30f;
            if (lane < p) {
                const float xv = __ldg(xr + lane);
                mN = fmaxf(mN, xv);
                mW = fmaxf(mW, __ldg(ynr + lane) ? xv : -1e30f);
            }
            if (lane < ntail) {
                const int j = ts + lane;
                const float xv = __ldg(xr + j);
                mN = fmaxf(mN, xv);
                mW = fmaxf(mW, __ldg(ynr + j) ? xv : -1e30f);
            }
            {
                float4 xv[8];
                int4   nv0[4];
                #pragma unroll
                for (int k = 0; k < 8; k++) {
                    const int i = lane + k * 32;
                    xv[k] = (i < nv) ? __ldg((const float4*)(xr + p + 4 * i))
                                     : make_float4(-1e30f, -1e30f, -1e30f, -1e30f);
                }
                #pragma unroll
                for (int k = 0; k < 4; k++) {
                    const int i = lane + k * 32;
                    nv0[k] = (i < nv) ? __ldg((const int4*)(ynr + p + 4 * i))
                                      : make_int4(0, 0, 0, 0);
                }
                #pragma unroll
                for (int k = 0; k < 8; k++)
                    mN = fmaxf(mN, fmaxf(fmaxf(xv[k].x, xv[k].y),
                                         fmaxf(xv[k].z, xv[k].w)));
                #pragma unroll
                for (int k = 0; k < 4; k++) {
                    mW = fmaxf(mW, nv0[k].x ? xv[k].x : -1e30f);
                    mW = fmaxf(mW, nv0[k].y ? xv[k].y : -1e30f);
                    mW = fmaxf(mW, nv0[k].z ? xv[k].z : -1e30f);
                    mW = fmaxf(mW, nv0[k].w ? xv[k].w : -1e30f);
                }
                #pragma unroll
                for (int k = 4; k < 8; k++) {
                    const int i = lane + k * 32;
                    const int4 nn = (i < nv) ? __ldg((const int4*)(ynr + p + 4 * i))
                                             : make_int4(0, 0, 0, 0);
                    mW = fmaxf(mW, nn.x ? xv[k].x : -1e30f);
                    mW = fmaxf(mW, nn.y ? xv[k].y : -1e30f);
                    mW = fmaxf(mW, nn.z ? xv[k].z : -1e30f);
                    mW = fmaxf(mW, nn.w ? xv[k].w : -1e30f);
                }
            }
            // rare overflow (nv > 256)
            for (int i = 256 + lane; i < nv; i += 32) {
                const float4 xo = __ldg((const float4*)(xr  + p + 4 * i));
                const int4   no = __ldg((const int4*)  (ynr + p + 4 * i));
                mN = fmaxf(mN, fmaxf(fmaxf(xo.x, xo.y), fmaxf(xo.z, xo.w)));
                mW = fmaxf(mW, no.x ? xo.x : -1e30f);
                mW = fmaxf(mW, no.y ? xo.y : -1e30f);
                mW = fmaxf(mW, no.z ? xo.z : -1e30f);
                mW = fmaxf(mW, no.w ? xo.w : -1e30f);
            }
            #pragma unroll
            for (int off = 16; off > 0; off >>= 1) {
                mN = fmaxf(mN, __shfl_xor_sync(0xffffffffu, mN, off));
                mW = fmaxf(mW, __shfl_xor_sync(0xffffffffu, mW, off));
            }
            warp_loss = 0.5f * rank_loss_(0.5f, sigmoidf_(mN))
                      + 0.5f * rank_loss_(0.5f, sigmoidf_(mW));
        }
    } else if (row < B) {
        // ---------------- generic slow path: scan g_bits over [0, C) ----------
        const unsigned KNEG = enc_f(-1e30f);
        sG[wid][lane] = KNEG;
        __syncwarp();

        unsigned locNon = KNEG, locWrong = KNEG, locPres = 0u;
        for (int c = lane; c < C; c += 32) {
            const unsigned bits = g_bits[c];
            if (!bits) continue;
            const long long o = (long long)row * C + c;
            const float xv = __ldg(x + o);
            const unsigned key = enc_f(xv);
            locNon = max(locNon, key);
            if (__ldg(yneg + o) != 0) locWrong = max(locWrong, key);
            if (__ldg(y    + o) != 0) locPres |= bits;
            unsigned bb = bits;
            while (bb) {
                const int l = __ffs(bb) - 1;
                bb &= bb - 1u;
                atomicMax(&sG[wid][l], key);
            }
        }
        #pragma unroll
        for (int off = 16; off > 0; off >>= 1) {
            locNon   = max(locNon,   __shfl_xor_sync(0xffffffffu, locNon,   off));
            locWrong = max(locWrong, __shfl_xor_sync(0xffffffffu, locWrong, off));
            locPres |= __shfl_xor_sync(0xffffffffu, locPres, off);
        }
        __syncwarp();
        if (lane == 0) {
            if (locPres) {
                const int fl = __ffs(locPres) - 1;
                warp_loss = rank_loss_(sigmoidf_(dec_f(sG[wid][fl])), 0.5f);
            } else {
                warp_loss = 0.5f * rank_loss_(0.5f, sigmoidf_(dec_f(locNon)))
                          + 0.5f * rank_loss_(0.5f, sigmoidf_(dec_f(locWrong)));
            }
        }
    }

    if (lane == 0 && row < B) atomicAdd(&sSum, warp_loss);
    __syncthreads();
    if (threadIdx.x == 0) atomicAdd(out, sSum);
}

// ---------------------------------------------------------------------------
extern "C" void kernel_launch(void* const* d_in, const int* in_sizes, int n_in,
                              void* d_out, int out_size) {
    const float* x    = (const float*)d_in[0];
    const int*   y    = (const int*)d_in[1];
    const int*   yneg = (const int*)d_in[2];
    const void*  wl   = d_in[3];

    const int C = 9605;
    const int L = in_sizes[3] / C;            // 20
    const int B = in_sizes[0] / C;            // 4096

    float* out = (float*)d_out;

    const int nb = (C + 255) / 256;           // 38

    build_bits_kernel<<<nb, 256>>>(wl, C, L, out, out_size);
    finalize_kernel<<<1, 1024>>>(C, nb);
    row_loss_kernel<<<(B + 3) / 4, 128>>>(x, y, yneg, C, B, out);
}